// round 17
// baseline (speedup 1.0000x reference)
#include <cuda_runtime.h>
#include <cuda_fp16.h>
#include <cstdint>

// Problem constants (static per reference)
#define A_N    900      // anchors
#define P_N    13       // points
#define CAM_N  6        // cameras
#define LVL_N  4        // levels
#define CH     256      // channels
#define G_N    8        // groups (32 ch each)
#define SAMP   (P_N * CAM_N * LVL_N)   // 312 samples per anchor
#define PC     (P_N * CAM_N)           // 78 samples per level
#define THW    14960    // sum of H*W over levels
#define NWARP  16
#define FEAT_N (CAM_N * THW * CH)

// Level-1..3 region: rows [11264, 14960) per cam.
#define HI_ROW0   11264
#define HI_ROWS   3696
#define HI_FLOATS (CAM_N * HI_ROWS * CH)          // 5,677,056
#define CVT_CTAS  (HI_FLOATS / 8 / 256)           // 2772 exactly

__constant__ int c_H[LVL_N] = {64, 32, 16, 8};
__constant__ int c_W[LVL_N] = {176, 88, 44, 22};
__constant__ int c_S[LVL_N] = {0, 11264, 14080, 14784};

// fp16 copy of levels 1-3 only (level-0 region never touched).
__device__ __half d_feath[FEAT_N];

// ---------------- Kernel 1: fp32 -> fp16, LEVELS 1-3 ONLY (23 MB) ----------
__global__ __launch_bounds__(256)
void cvt_kernel(const float* __restrict__ f)
{
    asm volatile("griddepcontrol.launch_dependents;" ::: "memory");
    const unsigned t   = blockIdx.x * 256 + threadIdx.x;
    const unsigned per = HI_ROWS * CH / 8;        // units per cam (118272)
    const unsigned cam = t / per;
    const unsigned off = t - cam * per;
    const size_t i = ((size_t)cam * THW + HI_ROW0) * CH + (size_t)off * 8;

    const float4 a = __ldcs(reinterpret_cast<const float4*>(f + i));
    const float4 b = __ldcs(reinterpret_cast<const float4*>(f + i + 4));
    __half2 h[4];
    h[0] = __floats2half2_rn(a.x, a.y);
    h[1] = __floats2half2_rn(a.z, a.w);
    h[2] = __floats2half2_rn(b.x, b.y);
    h[3] = __floats2half2_rn(b.z, b.w);
    *reinterpret_cast<uint4*>(d_feath + i) = *reinterpret_cast<const uint4*>(h);
}

// fp32 corner combine for a float2 channel pair (Phase A).
__device__ __forceinline__ void acc_f2(
    const float2& a0, const float2& a1, const float2& a2, const float2& a3,
    const float4 cw, const float wg, float2& acc)
{
    acc.x += wg * (cw.x*a0.x + cw.y*a1.x + cw.z*a2.x + cw.w*a3.x);
    acc.y += wg * (cw.x*a0.y + cw.y*a1.y + cw.z*a2.y + cw.w*a3.y);
}

// fp16 sample segment: bilinear in HFMA2 on 2 half2 (one uint2 per corner),
// then fp32 FMA applies the group weight (identical math order to R11).
__device__ __forceinline__ void acc_h2(
    const uint2& u0, const uint2& u1, const uint2& u2, const uint2& u3,
    const uint4& cwp, const float wg, float2* acc)
{
    const __half2* c  = reinterpret_cast<const __half2*>(&cwp);
    const __half2* h0 = reinterpret_cast<const __half2*>(&u0);
    const __half2* h1 = reinterpret_cast<const __half2*>(&u1);
    const __half2* h2 = reinterpret_cast<const __half2*>(&u2);
    const __half2* h3 = reinterpret_cast<const __half2*>(&u3);
    #pragma unroll
    for (int j = 0; j < 2; j++) {
        __half2 v = __hmul2(c[0], h0[j]);
        v = __hfma2(c[1], h1[j], v);
        v = __hfma2(c[2], h2[j], v);
        v = __hfma2(c[3], h3[j], v);
        const float2 fv = __half22float2(v);
        acc[j].x = fmaf(wg, fv.x, acc[j].x);
        acc[j].y = fmaf(wg, fv.y, acc[j].y);
    }
}

// ---------------- Kernel 2: gather ----------------
// One CTA per anchor, 512 threads = 16 warps. Slots [0,78) = level 0 in fp32
// from the ORIGINAL feature (exact) BEFORE the PDL wait -> overlaps cvt;
// slots [78,312) = levels 1-3 in fp16 after the wait.
// All gather loads are LDG.64 (256 B/warp = 2 L1 wavefronts) instead of
// LDG.128 (4 wf): within-LDG replay wavefronts cost ~2.07 cyc vs 1.0, so
// halving wf-per-LDG raises the L1tex service ceiling; independent loads
// per warp double (16 in flight) at the same register cost.
__global__ __launch_bounds__(512, 2)
void daf_gather(const float* __restrict__ feature,   // [1,6,14960,256] fp32
                const float* __restrict__ points,    // [1,900,13,6,2]
                const float* __restrict__ weights,   // [1,900,13,6,4,8]
                float* __restrict__ out)             // [1,900,256]
{
    const int a   = blockIdx.x;
    const int tid = threadIdx.x;

    __shared__ int4   s_idx[SAMP];       // 4 corner row indices
    __shared__ float4 s_cwf[PC];         // fp32 corner weights (level 0)
    __shared__ uint4  s_cwh[SAMP];       // half2 corner weights (levels 1-3)
    __shared__ float  s_w  [SAMP][G_N];  // 8 group weights (fp32)
    __shared__ float  s_red[NWARP][CH];  // per-warp partials

    // ---------- Phase 1: per-sample metadata ----------
    if (tid < SAMP) {
        const int s      = tid;
        const int lvl    = s / PC;          // level-major order 0,1,2,3
        const int within = s - lvl * PC;
        const int pt     = within / CAM_N;
        const int cam    = within - pt * CAM_N;

        const float2 p = *reinterpret_cast<const float2*>(
            points + (((size_t)a * P_N + pt) * CAM_N + cam) * 2);

        const int h = c_H[lvl], w = c_W[lvl];
        const float x = p.x * (float)w - 0.5f;
        const float y = p.y * (float)h - 0.5f;
        const float x0f = floorf(x), y0f = floorf(y);
        const int   x0  = (int)x0f,  y0  = (int)y0f;
        const float fx  = x - x0f,   fy  = y - y0f;
        const float wx[2] = {1.0f - fx, fx};
        const float wy[2] = {1.0f - fy, fy};
        const int base = cam * THW + c_S[lvl];

        int   vi[4];
        float vc[4];
        #pragma unroll
        for (int k = 0; k < 4; k++) {
            const int dx = k & 1, dy = k >> 1;
            const int xi = x0 + dx, yi = y0 + dy;
            const bool valid = (xi >= 0) & (xi < w) & (yi >= 0) & (yi < h);
            const int xc = min(max(xi, 0), w - 1);
            const int yc = min(max(yi, 0), h - 1);
            vi[k] = base + yc * w + xc;
            vc[k] = valid ? wx[dx] * wy[dy] : 0.0f;
        }
        s_idx[s] = make_int4(vi[0], vi[1], vi[2], vi[3]);
        if (lvl == 0) {
            s_cwf[s] = make_float4(vc[0], vc[1], vc[2], vc[3]);
        } else {
            __half2 hc[4];
            #pragma unroll
            for (int k = 0; k < 4; k++) hc[k] = __float2half2_rn(vc[k]);
            s_cwh[s] = *reinterpret_cast<const uint4*>(hc);
        }

        const float4* wp = reinterpret_cast<const float4*>(
            weights + ((((size_t)a * P_N + pt) * CAM_N + cam) * LVL_N + lvl) * G_N);
        float4* wd = reinterpret_cast<float4*>(&s_w[s][0]);
        wd[0] = wp[0];
        wd[1] = wp[1];
    }
    __syncthreads();

    const int warp = tid >> 5;
    const int lane = tid & 31;

    // ---------- Phase A: level 0 in fp32, LDG.64 (overlaps cvt) ----------
    // Warp pairs split the 1KB row: half = warp>>3 owns channels
    // [half*128, half*128+128) as 2 segments of 64; lane owns float2
    // channels {half*128 + seg*64 + 2*lane}.
    {
        const int sub    = warp & 7;
        const int half   = warp >> 3;
        const int base_c = half * 128 + lane * 2;
        const int g0     = half * 4 + (lane >> 4);   // group for seg 0; seg1 = g0+2

        float2 acc0 = make_float2(0.f, 0.f);
        float2 acc1 = make_float2(0.f, 0.f);

        #define LD2(row, seg) \
            (*(reinterpret_cast<const float2*>(feature + (size_t)(row) * CH + base_c) + (seg) * 32))

        int i = sub;
        for (; i + 8 < PC; i += 16) {
            const int j = i + 8;
            const int4 ia = s_idx[i];
            const int4 ib = s_idx[j];

            // 16 independent LDG.64 (2 samples x 4 corners x 2 segments)
            const float2 a00 = LD2(ia.x, 0), a01 = LD2(ia.x, 1);
            const float2 a10 = LD2(ia.y, 0), a11 = LD2(ia.y, 1);
            const float2 a20 = LD2(ia.z, 0), a21 = LD2(ia.z, 1);
            const float2 a30 = LD2(ia.w, 0), a31 = LD2(ia.w, 1);
            const float2 b00 = LD2(ib.x, 0), b01 = LD2(ib.x, 1);
            const float2 b10 = LD2(ib.y, 0), b11 = LD2(ib.y, 1);
            const float2 b20 = LD2(ib.z, 0), b21 = LD2(ib.z, 1);
            const float2 b30 = LD2(ib.w, 0), b31 = LD2(ib.w, 1);

            const float4 cwa = s_cwf[i];
            acc_f2(a00, a10, a20, a30, cwa, s_w[i][g0],     acc0);
            acc_f2(a01, a11, a21, a31, cwa, s_w[i][g0 + 2], acc1);
            const float4 cwb = s_cwf[j];
            acc_f2(b00, b10, b20, b30, cwb, s_w[j][g0],     acc0);
            acc_f2(b01, b11, b21, b31, cwb, s_w[j][g0 + 2], acc1);
        }
        if (i < PC) {
            const int4 ia = s_idx[i];
            const float2 a00 = LD2(ia.x, 0), a01 = LD2(ia.x, 1);
            const float2 a10 = LD2(ia.y, 0), a11 = LD2(ia.y, 1);
            const float2 a20 = LD2(ia.z, 0), a21 = LD2(ia.z, 1);
            const float2 a30 = LD2(ia.w, 0), a31 = LD2(ia.w, 1);
            const float4 cwa = s_cwf[i];
            acc_f2(a00, a10, a20, a30, cwa, s_w[i][g0],     acc0);
            acc_f2(a01, a11, a21, a31, cwa, s_w[i][g0 + 2], acc1);
        }
        #undef LD2

        // Seed this warp's s_red row: own half = acc, other half = 0.
        float* row = &s_red[warp][0];
        *reinterpret_cast<float2*>(row + base_c)      = acc0;
        *reinterpret_cast<float2*>(row + base_c + 64) = acc1;
        const int oc = (half ^ 1) * 128 + lane * 2;
        *reinterpret_cast<float2*>(row + oc)      = make_float2(0.f, 0.f);
        *reinterpret_cast<float2*>(row + oc + 64) = make_float2(0.f, 0.f);
    }
    __syncwarp();

    // ---------- Phase B: levels 1-3 in fp16, LDG.64 (after cvt) ----------
    asm volatile("griddepcontrol.wait;" ::: "memory");
    {
        const int gb = lane >> 3;   // group base; seg s -> group s*4 + gb

        float2 acc[2][2] = {{{0.f,0.f},{0.f,0.f}},{{0.f,0.f},{0.f,0.f}}};

        #define LDH(row, seg) \
            (*(reinterpret_cast<const uint2*>(d_feath + (size_t)(row) * CH + (seg) * 128) + lane))

        int i = PC + warp;
        for (; i + NWARP < SAMP; i += 2 * NWARP) {
            const int j = i + NWARP;
            const int4 ia = s_idx[i];
            const int4 ib = s_idx[j];

            // 16 independent LDG.64 (2 samples x 4 corners x 2 segments)
            const uint2 pa00 = LDH(ia.x, 0), pa01 = LDH(ia.x, 1);
            const uint2 pa10 = LDH(ia.y, 0), pa11 = LDH(ia.y, 1);
            const uint2 pa20 = LDH(ia.z, 0), pa21 = LDH(ia.z, 1);
            const uint2 pa30 = LDH(ia.w, 0), pa31 = LDH(ia.w, 1);
            const uint2 pb00 = LDH(ib.x, 0), pb01 = LDH(ib.x, 1);
            const uint2 pb10 = LDH(ib.y, 0), pb11 = LDH(ib.y, 1);
            const uint2 pb20 = LDH(ib.z, 0), pb21 = LDH(ib.z, 1);
            const uint2 pb30 = LDH(ib.w, 0), pb31 = LDH(ib.w, 1);

            const uint4 cwa = s_cwh[i];
            acc_h2(pa00, pa10, pa20, pa30, cwa, s_w[i][gb],     acc[0]);
            acc_h2(pa01, pa11, pa21, pa31, cwa, s_w[i][4 + gb], acc[1]);
            const uint4 cwb = s_cwh[j];
            acc_h2(pb00, pb10, pb20, pb30, cwb, s_w[j][gb],     acc[0]);
            acc_h2(pb01, pb11, pb21, pb31, cwb, s_w[j][4 + gb], acc[1]);
        }
        if (i < SAMP) {
            const int4 ia = s_idx[i];
            const uint2 pa00 = LDH(ia.x, 0), pa01 = LDH(ia.x, 1);
            const uint2 pa10 = LDH(ia.y, 0), pa11 = LDH(ia.y, 1);
            const uint2 pa20 = LDH(ia.z, 0), pa21 = LDH(ia.z, 1);
            const uint2 pa30 = LDH(ia.w, 0), pa31 = LDH(ia.w, 1);
            const uint4 cwa = s_cwh[i];
            acc_h2(pa00, pa10, pa20, pa30, cwa, s_w[i][gb],     acc[0]);
            acc_h2(pa01, pa11, pa21, pa31, cwa, s_w[i][4 + gb], acc[1]);
        }
        #undef LDH

        // Add the fp16-phase partial into this warp's s_red row:
        // seg s covers channels [s*128 + 4*lane, +4) -> float4 slot s*32+lane.
        float4* row4 = reinterpret_cast<float4*>(&s_red[warp][0]);
        #pragma unroll
        for (int s = 0; s < 2; s++) {
            float4 r = row4[s * 32 + lane];
            r.x += acc[s][0].x;  r.y += acc[s][0].y;
            r.z += acc[s][1].x;  r.w += acc[s][1].y;
            row4[s * 32 + lane] = r;
        }
    }
    __syncthreads();

    // ---------- Phase 3: reduce 16 warps, write output ----------
    if (tid < 64) {
        float4 r = make_float4(0.f, 0.f, 0.f, 0.f);
        #pragma unroll
        for (int w = 0; w < NWARP; w++) {
            const float4 t = reinterpret_cast<const float4*>(&s_red[w][0])[tid];
            r.x += t.x; r.y += t.y; r.z += t.z; r.w += t.w;
        }
        reinterpret_cast<float4*>(out + (size_t)a * CH)[tid] = r;
    }
}

extern "C" void kernel_launch(void* const* d_in, const int* in_sizes, int n_in,
                              void* d_out, int out_size)
{
    const float* feature = (const float*)d_in[0];
    // d_in[1] = spatial_shapes, d_in[2] = level_start_index (static, hardcoded)
    const float* points  = (const float*)d_in[3];
    const float* weights = (const float*)d_in[4];
    float* out = (float*)d_out;

    cvt_kernel<<<CVT_CTAS, 256>>>(feature);

    // PDL: gather starts early; its level-0 fp32 phase needs no conversion
    // and overlaps cvt; griddepcontrol.wait gates the fp16 reads only.
    cudaLaunchConfig_t cfg = {};
    cfg.gridDim  = dim3(A_N);
    cfg.blockDim = dim3(512);
    cfg.stream   = 0;
    cudaLaunchAttribute attr[1];
    attr[0].id = cudaLaunchAttributeProgrammaticStreamSerialization;
    attr[0].val.programmaticStreamSerializationAllowed = 1;
    cfg.attrs = attr;
    cfg.numAttrs = 1;
    cudaLaunchKernelEx(&cfg, daf_gather, feature, points, weights, out);
}